// round 3
// baseline (speedup 1.0000x reference)
#include <cuda_runtime.h>
#include <cstdint>
#include <cstddef>

#define N_NODES 100000
#define N_EDGES 600000
#define DIM_D 128
#define DIM_H 256

// ---------------- scratch (device globals: no allocation allowed) ----------
__device__ float g_H0[(size_t)N_NODES * DIM_D];   // h after aggregation; reused as X2
__device__ float g_X1[(size_t)N_NODES * DIM_H];   // first MLP layer raw output
__device__ float g_sum1[DIM_H];
__device__ float g_sq1[DIM_H];
__device__ float g_sum2[DIM_D];
__device__ float g_sq2[DIM_D];
__device__ float g_s1[DIM_H];
__device__ float g_t1[DIM_H];
__device__ float g_s2[DIM_D];
__device__ float g_t2[DIM_D];

// ---------------- kernels --------------------------------------------------

__global__ void k_zero_stats() {
    int t = threadIdx.x;
    if (t < DIM_H) { g_sum1[t] = 0.f; g_sq1[t] = 0.f; }
    if (t < DIM_D) { g_sum2[t] = 0.f; g_sq2[t] = 0.f; }
}

// h_init[n,:] = (1 + eps - degree[n]) * node_rep[n,:]
__global__ void k_init_h(const float* __restrict__ nr,
                         const float* __restrict__ deg,
                         const float* __restrict__ eps) {
    int idx = blockIdx.x * blockDim.x + threadIdx.x;   // float4 index
    if (idx >= N_NODES * (DIM_D / 4)) return;
    int row = idx >> 5;                                // 32 float4 per row
    float c = 1.0f + eps[0] - deg[row];
    float4 v = reinterpret_cast<const float4*>(nr)[idx];
    reinterpret_cast<float4*>(g_H0)[idx] =
        make_float4(c * v.x, c * v.y, c * v.z, c * v.w);
}

__device__ __forceinline__ void red_add_v4(float* addr, float4 v) {
    asm volatile("red.global.add.v4.f32 [%0], {%1,%2,%3,%4};"
                 :: "l"(addr), "f"(v.x), "f"(v.y), "f"(v.z), "f"(v.w)
                 : "memory");
}

// one warp per edge: m = nr[src]+nr[dst]+ea; scatter-add to both endpoints
__global__ void k_edge_scatter(const float* __restrict__ nr,
                               const float* __restrict__ ea,
                               const int* __restrict__ src,
                               const int* __restrict__ dst) {
    int e = blockIdx.x * 8 + (threadIdx.x >> 5);
    if (e >= N_EDGES) return;
    int lane = threadIdx.x & 31;
    int s = src[e];
    int d = dst[e];
    float4 a = *(reinterpret_cast<const float4*>(nr + (size_t)s * DIM_D) + lane);
    float4 b = *(reinterpret_cast<const float4*>(nr + (size_t)d * DIM_D) + lane);
    float4 c = *(reinterpret_cast<const float4*>(ea + (size_t)e * DIM_D) + lane);
    float4 m = make_float4(a.x + b.x + c.x, a.y + b.y + c.y,
                           a.z + b.z + c.z, a.w + b.w + c.w);
    red_add_v4(g_H0 + (size_t)s * DIM_D + lane * 4, m);
    red_add_v4(g_H0 + (size_t)d * DIM_D + lane * 4, m);
}

// ---------------- tf32 tensor-core GEMM ------------------------------------
// C[m,n] = sum_k A[m,k] * Bw[n,k]   (Bw row-major [Ntot,K] == W^T layout)
// Optionally applies y = relu(x*bnS[k] + bnT[k]) to A elements at load time.

__device__ __forceinline__ uint32_t f2tf32(float x) {
    uint32_t r;
    asm("cvt.rna.tf32.f32 %0, %1;" : "=r"(r) : "f"(x));
    return r;
}

__device__ __forceinline__ void mma_tf32(float* c, const uint32_t* a,
                                         uint32_t b0, uint32_t b1) {
    asm volatile(
        "mma.sync.aligned.m16n8k8.row.col.f32.tf32.tf32.f32 "
        "{%0,%1,%2,%3}, {%4,%5,%6,%7}, {%8,%9}, {%0,%1,%2,%3};"
        : "+f"(c[0]), "+f"(c[1]), "+f"(c[2]), "+f"(c[3])
        : "r"(a[0]), "r"(a[1]), "r"(a[2]), "r"(a[3]), "r"(b0), "r"(b1));
}

// Block tile 128x128, BK=32, 8 warps in 4(M)x2(N); warp tile 32x64.
// Smem stride 36 words => fragment LDS hit all 32 banks (conflict-free).
__global__ __launch_bounds__(256, 2)
void k_gemm_tf32(const float* __restrict__ A, const float* __restrict__ Bw,
                 float* __restrict__ C, int M, int Ntot, int K,
                 const float* __restrict__ bnS, const float* __restrict__ bnT) {
    __shared__ uint32_t As[128][36];
    __shared__ uint32_t Bs[128][36];
    const int tid  = threadIdx.x;
    const int warp = tid >> 5;
    const int lane = tid & 31;
    const int wm   = warp >> 1;      // 0..3
    const int wn   = warp & 1;       // 0..1
    const int g    = lane >> 2;      // groupID
    const int tg   = lane & 3;       // thread-in-group
    const int mbase = blockIdx.x * 128;
    const int nbase = blockIdx.y * 128;

    float acc[2][8][4];
    #pragma unroll
    for (int i = 0; i < 2; i++)
        #pragma unroll
        for (int j = 0; j < 8; j++)
            #pragma unroll
            for (int q = 0; q < 4; q++) acc[i][j][q] = 0.f;

    for (int k0 = 0; k0 < K; k0 += 32) {
        #pragma unroll
        for (int it = 0; it < 4; it++) {
            int idx = tid + it * 256;      // 0..1023 float4 slots
            int row = idx >> 3;
            int c4  = idx & 7;
            int kk  = k0 + c4 * 4;
            // A tile (guard M tail; apply BN+ReLU if requested)
            int grow = mbase + row;
            float4 v = make_float4(0.f, 0.f, 0.f, 0.f);
            if (grow < M)
                v = *reinterpret_cast<const float4*>(A + (size_t)grow * K + kk);
            if (bnS) {
                v.x = fmaxf(fmaf(v.x, bnS[kk + 0], bnT[kk + 0]), 0.f);
                v.y = fmaxf(fmaf(v.y, bnS[kk + 1], bnT[kk + 1]), 0.f);
                v.z = fmaxf(fmaf(v.z, bnS[kk + 2], bnT[kk + 2]), 0.f);
                v.w = fmaxf(fmaf(v.w, bnS[kk + 3], bnT[kk + 3]), 0.f);
            }
            uint32_t* pa = &As[row][c4 * 4];
            pa[0] = f2tf32(v.x); pa[1] = f2tf32(v.y);
            pa[2] = f2tf32(v.z); pa[3] = f2tf32(v.w);
            // B tile (Ntot is always a multiple of 128 here: no guard)
            float4 w = *reinterpret_cast<const float4*>(
                Bw + (size_t)(nbase + row) * K + kk);
            uint32_t* pb = &Bs[row][c4 * 4];
            pb[0] = f2tf32(w.x); pb[1] = f2tf32(w.y);
            pb[2] = f2tf32(w.z); pb[3] = f2tf32(w.w);
        }
        __syncthreads();
        #pragma unroll
        for (int ks = 0; ks < 4; ks++) {
            const int kc = ks * 8;
            uint32_t af[2][4];
            #pragma unroll
            for (int i = 0; i < 2; i++) {
                int r = wm * 32 + i * 16 + g;
                af[i][0] = As[r][kc + tg];
                af[i][1] = As[r + 8][kc + tg];
                af[i][2] = As[r][kc + tg + 4];
                af[i][3] = As[r + 8][kc + tg + 4];
            }
            #pragma unroll
            for (int j = 0; j < 8; j++) {
                int n = wn * 64 + j * 8 + g;
                uint32_t b0 = Bs[n][kc + tg];
                uint32_t b1 = Bs[n][kc + tg + 4];
                mma_tf32(acc[0][j], af[0], b0, b1);
                mma_tf32(acc[1][j], af[1], b0, b1);
            }
        }
        __syncthreads();
    }

    #pragma unroll
    for (int i = 0; i < 2; i++) {
        int r0 = mbase + wm * 32 + i * 16 + g;
        int r1 = r0 + 8;
        #pragma unroll
        for (int j = 0; j < 8; j++) {
            int c0 = nbase + wn * 64 + j * 8 + tg * 2;
            if (r0 < M)
                *reinterpret_cast<float2*>(C + (size_t)r0 * Ntot + c0) =
                    make_float2(acc[i][j][0], acc[i][j][1]);
            if (r1 < M)
                *reinterpret_cast<float2*>(C + (size_t)r1 * Ntot + c0) =
                    make_float2(acc[i][j][2], acc[i][j][3]);
        }
    }
}

// per-column sum / sum-of-squares (blockDim.x == C)
__global__ void k_col_stats(const float* __restrict__ X, int M, int C,
                            float* __restrict__ sum, float* __restrict__ sq) {
    int c = threadIdx.x;
    float s = 0.f, q = 0.f;
    for (int r = blockIdx.x; r < M; r += gridDim.x) {
        float v = X[(size_t)r * C + c];
        s += v;
        q += v * v;
    }
    atomicAdd(&sum[c], s);
    atomicAdd(&sq[c], q);
}

__global__ void k_bn_params(const float* __restrict__ sum,
                            const float* __restrict__ sq,
                            const float* __restrict__ gam,
                            const float* __restrict__ bet,
                            int C, float* __restrict__ oS, float* __restrict__ oT) {
    int c = threadIdx.x;
    if (c >= C) return;
    const float invN = 1.0f / (float)N_NODES;
    float mean = sum[c] * invN;
    float var  = sq[c] * invN - mean * mean;
    float s = gam[c] * rsqrtf(var + 1e-5f);
    oS[c] = s;
    oT[c] = bet[c] - mean * s;
}

// out = relu(bn2(X2)), X2 lives in g_H0
__global__ void k_final(const float* __restrict__ s2,
                        const float* __restrict__ t2,
                        float* __restrict__ out) {
    int idx = blockIdx.x * blockDim.x + threadIdx.x;
    if (idx >= N_NODES * (DIM_D / 4)) return;
    int c0 = (idx & 31) * 4;
    float4 v = reinterpret_cast<const float4*>(g_H0)[idx];
    float4 o;
    o.x = fmaxf(fmaf(v.x, s2[c0 + 0], t2[c0 + 0]), 0.f);
    o.y = fmaxf(fmaf(v.y, s2[c0 + 1], t2[c0 + 1]), 0.f);
    o.z = fmaxf(fmaf(v.z, s2[c0 + 2], t2[c0 + 2]), 0.f);
    o.w = fmaxf(fmaf(v.w, s2[c0 + 3], t2[c0 + 3]), 0.f);
    reinterpret_cast<float4*>(out)[idx] = o;
}

// ---------------- launch ----------------------------------------------------

extern "C" void kernel_launch(void* const* d_in, const int* in_sizes, int n_in,
                              void* d_out, int out_size) {
    const float* node_rep  = (const float*)d_in[0];
    const float* edge_attr = (const float*)d_in[1];
    const float* degree    = (const float*)d_in[2];
    const float* eps       = (const float*)d_in[3];
    const float* W1        = (const float*)d_in[4];
    const float* g1        = (const float*)d_in[5];
    const float* b1        = (const float*)d_in[6];
    const float* W2        = (const float*)d_in[7];
    const float* g2        = (const float*)d_in[8];
    const float* b2        = (const float*)d_in[9];
    const int*   src       = (const int*)d_in[10];
    const int*   dst       = (const int*)d_in[11];
    float* out = (float*)d_out;

    float *pH0, *pX1, *psum1, *psq1, *psum2, *psq2, *ps1, *pt1, *ps2, *pt2;
    cudaGetSymbolAddress((void**)&pH0, g_H0);
    cudaGetSymbolAddress((void**)&pX1, g_X1);
    cudaGetSymbolAddress((void**)&psum1, g_sum1);
    cudaGetSymbolAddress((void**)&psq1, g_sq1);
    cudaGetSymbolAddress((void**)&psum2, g_sum2);
    cudaGetSymbolAddress((void**)&psq2, g_sq2);
    cudaGetSymbolAddress((void**)&ps1, g_s1);
    cudaGetSymbolAddress((void**)&pt1, g_t1);
    cudaGetSymbolAddress((void**)&ps2, g_s2);
    cudaGetSymbolAddress((void**)&pt2, g_t2);

    k_zero_stats<<<1, 256>>>();
    k_init_h<<<(N_NODES * (DIM_D / 4) + 255) / 256, 256>>>(node_rep, degree, eps);
    k_edge_scatter<<<N_EDGES / 8, 256>>>(node_rep, edge_attr, src, dst);

    dim3 grid1((N_NODES + 127) / 128, DIM_H / 128);
    k_gemm_tf32<<<grid1, 256>>>(pH0, W1, pX1, N_NODES, DIM_H, DIM_D,
                                nullptr, nullptr);
    k_col_stats<<<512, DIM_H>>>(pX1, N_NODES, DIM_H, psum1, psq1);
    k_bn_params<<<1, DIM_H>>>(psum1, psq1, g1, b1, DIM_H, ps1, pt1);

    dim3 grid2((N_NODES + 127) / 128, DIM_D / 128);
    k_gemm_tf32<<<grid2, 256>>>(pX1, W2, pH0, N_NODES, DIM_D, DIM_H,
                                ps1, pt1);
    k_col_stats<<<512, DIM_D>>>(pH0, N_NODES, DIM_D, psum2, psq2);
    k_bn_params<<<1, DIM_D>>>(psum2, psq2, g2, b2, DIM_D, ps2, pt2);

    k_final<<<(N_NODES * (DIM_D / 4) + 255) / 256, 256>>>(ps2, pt2, out);
}

// round 5
// speedup vs baseline: 1.6019x; 1.6019x over previous
#include <cuda_runtime.h>
#include <cstdint>
#include <cstddef>

#define N_NODES 100000
#define MPAD    100096            // 782 * 128
#define N_EDGES 600000
#define DIM_D 128
#define DIM_H 256

// ---------------- scratch (device globals: no allocation allowed) ----------
__device__ __align__(256) float g_H0[(size_t)MPAD * DIM_D];   // h (agg); reused as X2
__device__ __align__(256) float g_X1[(size_t)MPAD * DIM_H];   // layer-1 raw out; then tf32(bnrelu)
__device__ __align__(256) uint32_t g_W1t[DIM_H * DIM_D];      // tf32 weights
__device__ __align__(256) uint32_t g_W2t[DIM_D * DIM_H];
__device__ float g_sum1[DIM_H];
__device__ float g_sq1[DIM_H];
__device__ float g_sum2[DIM_D];
__device__ float g_sq2[DIM_D];
__device__ float g_s1[DIM_H];
__device__ float g_t1[DIM_H];
__device__ float g_s2[DIM_D];
__device__ float g_t2[DIM_D];

__device__ __forceinline__ uint32_t f2tf32(float x) {
    uint32_t r;
    asm("cvt.rna.tf32.f32 %0, %1;" : "=r"(r) : "f"(x));
    return r;
}

// ---------------- graph aggregation ----------------------------------------

// H0[n,:] = (1 + eps - degree[n]) * node_rep[n,:]; pad rows = 0; zero stats
__global__ void k_init(const float* __restrict__ nr,
                       const float* __restrict__ deg,
                       const float* __restrict__ eps) {
    if (blockIdx.x == 0) {
        int t = threadIdx.x;
        if (t < DIM_H) { g_sum1[t] = 0.f; g_sq1[t] = 0.f; }
        if (t < DIM_D) { g_sum2[t] = 0.f; g_sq2[t] = 0.f; }
    }
    int idx = blockIdx.x * blockDim.x + threadIdx.x;   // float4 index
    if (idx >= MPAD * (DIM_D / 4)) return;
    int row = idx >> 5;                                // 32 float4 per row
    float4 o = make_float4(0.f, 0.f, 0.f, 0.f);
    if (row < N_NODES) {
        float c = 1.0f + eps[0] - deg[row];
        float4 v = reinterpret_cast<const float4*>(nr)[idx];
        o = make_float4(c * v.x, c * v.y, c * v.z, c * v.w);
    }
    reinterpret_cast<float4*>(g_H0)[idx] = o;
}

__device__ __forceinline__ void red_add_v4(float* addr, float4 v) {
    asm volatile("red.global.add.v4.f32 [%0], {%1,%2,%3,%4};"
                 :: "l"(addr), "f"(v.x), "f"(v.y), "f"(v.z), "f"(v.w)
                 : "memory");
}

// one warp per edge: m = nr[src]+nr[dst]+ea; scatter-add to both endpoints.
// edge_attr is a one-shot 307MB stream -> evict-streaming load so the
// L2-resident node table (nr + H0) stays hot for the random gathers/atomics.
__global__ void k_edge_scatter(const float* __restrict__ nr,
                               const float* __restrict__ ea,
                               const int* __restrict__ src,
                               const int* __restrict__ dst) {
    int e = blockIdx.x * 8 + (threadIdx.x >> 5);
    if (e >= N_EDGES) return;
    int lane = threadIdx.x & 31;
    int s = src[e];
    int d = dst[e];
    float4 a = __ldg(reinterpret_cast<const float4*>(nr + (size_t)s * DIM_D) + lane);
    float4 b = __ldg(reinterpret_cast<const float4*>(nr + (size_t)d * DIM_D) + lane);
    float4 c = __ldcs(reinterpret_cast<const float4*>(ea + (size_t)e * DIM_D) + lane);
    float4 m = make_float4(a.x + b.x + c.x, a.y + b.y + c.y,
                           a.z + b.z + c.z, a.w + b.w + c.w);
    red_add_v4(g_H0 + (size_t)s * DIM_D + lane * 4, m);
    red_add_v4(g_H0 + (size_t)d * DIM_D + lane * 4, m);
}

// in-place round H0 to tf32 bit pattern (enables raw cp.async into the GEMM)
__global__ void k_cvt_h0() {
    int idx = blockIdx.x * blockDim.x + threadIdx.x;
    if (idx >= MPAD * (DIM_D / 4)) return;
    float4 v = reinterpret_cast<const float4*>(g_H0)[idx];
    uint4 o;
    o.x = f2tf32(v.x); o.y = f2tf32(v.y); o.z = f2tf32(v.z); o.w = f2tf32(v.w);
    reinterpret_cast<uint4*>(g_H0)[idx] = o;
}

// weights -> tf32 (both fit in one tiny grid)
__global__ void k_cvt_w(const float* __restrict__ W1, const float* __restrict__ W2) {
    int i = blockIdx.x * blockDim.x + threadIdx.x;
    if (i < DIM_H * DIM_D) {
        g_W1t[i] = f2tf32(W1[i]);
        g_W2t[i] = f2tf32(W2[i]);
    }
}

// ---------------- tf32 tensor-core GEMM, cp.async 3-stage pipeline ---------
// C[m,n] = sum_k A[m,k] * B[n,k].  A and B already hold tf32 bit patterns.
// Block 128x128, BK=32, 8 warps 4(M)x2(N), warp tile 32x64.
// Epilogue: store C (f32) and atomically accumulate per-column sum / sum-sq.

#define GSTAGES 3
#define TILE_WORDS (128 * 36)                   // one operand tile (padded)
#define STAGE_WORDS (2 * TILE_WORDS)            // A + B
#define GEMM_SMEM_BYTES (GSTAGES * STAGE_WORDS * 4)

__global__ __launch_bounds__(256, 2)
void k_gemm(const float* __restrict__ A, const uint32_t* __restrict__ Bt,
            float* __restrict__ C, int Ntot, int K,
            float* __restrict__ osum, float* __restrict__ osq) {
    extern __shared__ uint32_t sm[];
    const int tid  = threadIdx.x;
    const int warp = tid >> 5;
    const int lane = tid & 31;
    const int wm   = warp >> 1;
    const int wn   = warp & 1;
    const int g    = lane >> 2;
    const int tg   = lane & 3;
    const int mbase = blockIdx.y * 128;
    const int nbase = blockIdx.x * 128;

    int frow[4], fcol[4];
    #pragma unroll
    for (int it = 0; it < 4; it++) {
        int idx = tid + it * 256;
        frow[it] = idx >> 3;
        fcol[it] = (idx & 7) * 4;
    }
    const int iters = K >> 5;

    float acc[2][8][4] = {};

    // --- pipeline helpers -------------------------------------------------
    auto issue = [&](int i) {
        uint32_t* as = sm + (i % GSTAGES) * STAGE_WORDS;
        uint32_t* bs = as + TILE_WORDS;
        #pragma unroll
        for (int it = 0; it < 4; it++) {
            const float*    ga = A  + (size_t)(mbase + frow[it]) * K + i * 32 + fcol[it];
            const uint32_t* gb = Bt + (size_t)(nbase + frow[it]) * K + i * 32 + fcol[it];
            uint32_t da = (uint32_t)__cvta_generic_to_shared(as + frow[it] * 36 + fcol[it]);
            uint32_t db = (uint32_t)__cvta_generic_to_shared(bs + frow[it] * 36 + fcol[it]);
            asm volatile("cp.async.cg.shared.global [%0], [%1], 16;" :: "r"(da), "l"(ga));
            asm volatile("cp.async.cg.shared.global [%0], [%1], 16;" :: "r"(db), "l"(gb));
        }
        asm volatile("cp.async.commit_group;");
    };

    issue(0);
    issue(1);

    for (int i = 0; i < iters; i++) {
        asm volatile("cp.async.wait_group 1;");
        __syncthreads();
        if (i + 2 < iters) issue(i + 2);
        else asm volatile("cp.async.commit_group;");   // keep group count in step

        const uint32_t* as = sm + (i % GSTAGES) * STAGE_WORDS;
        const uint32_t* bs = as + TILE_WORDS;
        #pragma unroll
        for (int ks = 0; ks < 4; ks++) {
            const int kc = ks * 8;
            uint32_t af[2][4];
            #pragma unroll
            for (int ii = 0; ii < 2; ii++) {
                int r = wm * 32 + ii * 16 + g;
                af[ii][0] = as[r * 36 + kc + tg];
                af[ii][1] = as[(r + 8) * 36 + kc + tg];
                af[ii][2] = as[r * 36 + kc + tg + 4];
                af[ii][3] = as[(r + 8) * 36 + kc + tg + 4];
            }
            #pragma unroll
            for (int j = 0; j < 8; j++) {
                int n = wn * 64 + j * 8 + g;
                uint32_t b0 = bs[n * 36 + kc + tg];
                uint32_t b1 = bs[n * 36 + kc + tg + 4];
                asm volatile(
                    "mma.sync.aligned.m16n8k8.row.col.f32.tf32.tf32.f32 "
                    "{%0,%1,%2,%3}, {%4,%5,%6,%7}, {%8,%9}, {%0,%1,%2,%3};"
                    : "+f"(acc[0][j][0]), "+f"(acc[0][j][1]),
                      "+f"(acc[0][j][2]), "+f"(acc[0][j][3])
                    : "r"(af[0][0]), "r"(af[0][1]), "r"(af[0][2]), "r"(af[0][3]),
                      "r"(b0), "r"(b1));
                asm volatile(
                    "mma.sync.aligned.m16n8k8.row.col.f32.tf32.tf32.f32 "
                    "{%0,%1,%2,%3}, {%4,%5,%6,%7}, {%8,%9}, {%0,%1,%2,%3};"
                    : "+f"(acc[1][j][0]), "+f"(acc[1][j][1]),
                      "+f"(acc[1][j][2]), "+f"(acc[1][j][3])
                    : "r"(af[1][0]), "r"(af[1][1]), "r"(af[1][2]), "r"(af[1][3]),
                      "r"(b0), "r"(b1));
            }
        }
        __syncthreads();
    }

    // --- store C (no guards: M padded, N multiple of 128) -----------------
    #pragma unroll
    for (int ii = 0; ii < 2; ii++) {
        int r0 = mbase + wm * 32 + ii * 16 + g;
        int r1 = r0 + 8;
        #pragma unroll
        for (int j = 0; j < 8; j++) {
            int c0 = nbase + wn * 64 + j * 8 + tg * 2;
            *reinterpret_cast<float2*>(C + (size_t)r0 * Ntot + c0) =
                make_float2(acc[ii][j][0], acc[ii][j][1]);
            *reinterpret_cast<float2*>(C + (size_t)r1 * Ntot + c0) =
                make_float2(acc[ii][j][2], acc[ii][j][3]);
        }
    }

    // --- fused column stats: reduce 32 warp-tile rows, atomic to global ---
    #pragma unroll
    for (int j = 0; j < 8; j++) {
        #pragma unroll
        for (int q = 0; q < 2; q++) {
            float a0 = acc[0][j][q],     a1 = acc[0][j][q + 2];
            float a2 = acc[1][j][q],     a3 = acc[1][j][q + 2];
            float s  = a0 + a1 + a2 + a3;
            float ss = a0 * a0 + a1 * a1 + a2 * a2 + a3 * a3;
            #pragma unroll
            for (int o = 4; o < 32; o <<= 1) {
                s  += __shfl_xor_sync(0xffffffffu, s,  o);
                ss += __shfl_xor_sync(0xffffffffu, ss, o);
            }
            if (g == 0) {
                int c = nbase + wn * 64 + j * 8 + tg * 2 + q;
                atomicAdd(&osum[c], s);
                atomicAdd(&osq[c], ss);
            }
        }
    }
}

// ---------------- BN params ------------------------------------------------

__global__ void k_bn_params(const float* __restrict__ sum,
                            const float* __restrict__ sq,
                            const float* __restrict__ gam,
                            const float* __restrict__ bet,
                            int C, float* __restrict__ oS, float* __restrict__ oT) {
    int c = threadIdx.x;
    if (c >= C) return;
    const float invN = 1.0f / (float)N_NODES;
    float mean = sum[c] * invN;
    float var  = sq[c] * invN - mean * mean;
    float s = gam[c] * rsqrtf(var + 1e-5f);
    oS[c] = s;
    oT[c] = bet[c] - mean * s;
}

// X1 <- tf32(relu(bn1(X1))) in place; pad rows forced to 0 so GEMM2 stats stay clean
__global__ void k_bnrelu_cvt(const float* __restrict__ s1,
                             const float* __restrict__ t1) {
    int idx = blockIdx.x * blockDim.x + threadIdx.x;   // float4 index over [MPAD,256]
    if (idx >= MPAD * (DIM_H / 4)) return;
    int row = idx >> 6;                                // 64 float4 per row
    uint4 o = make_uint4(0u, 0u, 0u, 0u);
    if (row < N_NODES) {
        int c0 = (idx & 63) * 4;
        float4 v = reinterpret_cast<const float4*>(g_X1)[idx];
        o.x = f2tf32(fmaxf(fmaf(v.x, s1[c0 + 0], t1[c0 + 0]), 0.f));
        o.y = f2tf32(fmaxf(fmaf(v.y, s1[c0 + 1], t1[c0 + 1]), 0.f));
        o.z = f2tf32(fmaxf(fmaf(v.z, s1[c0 + 2], t1[c0 + 2]), 0.f));
        o.w = f2tf32(fmaxf(fmaf(v.w, s1[c0 + 3], t1[c0 + 3]), 0.f));
    }
    reinterpret_cast<uint4*>(g_X1)[idx] = o;
}

// out = relu(bn2(X2)), X2 lives in g_H0 (f32, raw GEMM2 output)
__global__ void k_final(const float* __restrict__ s2,
                        const float* __restrict__ t2,
                        float* __restrict__ out) {
    int idx = blockIdx.x * blockDim.x + threadIdx.x;
    if (idx >= N_NODES * (DIM_D / 4)) return;
    int c0 = (idx & 31) * 4;
    float4 v = reinterpret_cast<const float4*>(g_H0)[idx];
    float4 o;
    o.x = fmaxf(fmaf(v.x, s2[c0 + 0], t2[c0 + 0]), 0.f);
    o.y = fmaxf(fmaf(v.y, s2[c0 + 1], t2[c0 + 1]), 0.f);
    o.z = fmaxf(fmaf(v.z, s2[c0 + 2], t2[c0 + 2]), 0.f);
    o.w = fmaxf(fmaf(v.w, s2[c0 + 3], t2[c0 + 3]), 0.f);
    reinterpret_cast<float4*>(out)[idx] = o;
}

// ---------------- launch ----------------------------------------------------

extern "C" void kernel_launch(void* const* d_in, const int* in_sizes, int n_in,
                              void* d_out, int out_size) {
    const float* node_rep  = (const float*)d_in[0];
    const float* edge_attr = (const float*)d_in[1];
    const float* degree    = (const float*)d_in[2];
    const float* eps       = (const float*)d_in[3];
    const float* W1        = (const float*)d_in[4];
    const float* gam1      = (const float*)d_in[5];
    const float* bet1      = (const float*)d_in[6];
    const float* W2        = (const float*)d_in[7];
    const float* gam2      = (const float*)d_in[8];
    const float* bet2      = (const float*)d_in[9];
    const int*   src       = (const int*)d_in[10];
    const int*   dst       = (const int*)d_in[11];
    float* out = (float*)d_out;

    float *pH0, *pX1, *psum1, *psq1, *psum2, *psq2, *ps1, *pt1, *ps2, *pt2;
    uint32_t *pW1t, *pW2t;
    cudaGetSymbolAddress((void**)&pH0, g_H0);
    cudaGetSymbolAddress((void**)&pX1, g_X1);
    cudaGetSymbolAddress((void**)&pW1t, g_W1t);
    cudaGetSymbolAddress((void**)&pW2t, g_W2t);
    cudaGetSymbolAddress((void**)&psum1, g_sum1);
    cudaGetSymbolAddress((void**)&psq1, g_sq1);
    cudaGetSymbolAddress((void**)&psum2, g_sum2);
    cudaGetSymbolAddress((void**)&psq2, g_sq2);
    cudaGetSymbolAddress((void**)&ps1, g_s1);
    cudaGetSymbolAddress((void**)&pt1, g_t1);
    cudaGetSymbolAddress((void**)&ps2, g_s2);
    cudaGetSymbolAddress((void**)&pt2, g_t2);

    cudaFuncSetAttribute(k_gemm, cudaFuncAttributeMaxDynamicSharedMemorySize,
                         GEMM_SMEM_BYTES);

    k_init<<<(MPAD * (DIM_D / 4) + 255) / 256, 256>>>(node_rep, degree, eps);
    k_cvt_w<<<(DIM_H * DIM_D + 255) / 256, 256>>>(W1, W2);
    k_edge_scatter<<<N_EDGES / 8, 256>>>(node_rep, edge_attr, src, dst);
    k_cvt_h0<<<(MPAD * (DIM_D / 4) + 255) / 256, 256>>>();

    dim3 grid1(DIM_H / 128, MPAD / 128);   // x fastest -> A tile L2 reuse
    k_gemm<<<grid1, 256, GEMM_SMEM_BYTES>>>((const float*)pH0, pW1t, pX1,
                                            DIM_H, DIM_D, psum1, psq1);
    k_bn_params<<<1, DIM_H>>>(psum1, psq1, gam1, bet1, DIM_H, ps1, pt1);
    k_bnrelu_cvt<<<(MPAD * (DIM_H / 4) + 255) / 256, 256>>>(ps1, pt1);

    dim3 grid2(DIM_D / 128, MPAD / 128);
    k_gemm<<<grid2, 256, GEMM_SMEM_BYTES>>>((const float*)pX1, pW2t, pH0,
                                            DIM_D, DIM_H, psum2, psq2);
    k_bn_params<<<1, DIM_D>>>(psum2, psq2, gam2, bet2, DIM_D, ps2, pt2);

    k_final<<<(N_NODES * (DIM_D / 4) + 255) / 256, 256>>>(ps2, pt2, out);
}

// round 6
// speedup vs baseline: 1.7277x; 1.0785x over previous
#include <cuda_runtime.h>
#include <cstdint>
#include <cstddef>

#define N_NODES 100000
#define MPAD    100096            // 782 * 128
#define N_EDGES 600000
#define DIM_D 128
#define DIM_H 256

// ---------------- scratch (device globals: no allocation allowed) ----------
__device__ __align__(256) float g_H0[(size_t)MPAD * DIM_D];   // h (agg, f32); reused as X2
__device__ __align__(256) float g_X1[(size_t)MPAD * DIM_H];   // layer-1 raw output (f32)
__device__ __align__(256) uint32_t g_W1t[DIM_H * DIM_D];      // tf32 weights
__device__ __align__(256) uint32_t g_W2t[DIM_D * DIM_H];
__device__ float g_sum1[DIM_H];
__device__ float g_sq1[DIM_H];
__device__ float g_sum2[DIM_D];
__device__ float g_sq2[DIM_D];
__device__ float g_s1[DIM_H];
__device__ float g_t1[DIM_H];
__device__ float g_s2[DIM_D];
__device__ float g_t2[DIM_D];

__device__ __forceinline__ uint32_t f2tf32(float x) {
    uint32_t r;
    asm("cvt.rna.tf32.f32 %0, %1;" : "=r"(r) : "f"(x));
    return r;
}

// ---------------- graph aggregation ----------------------------------------

// H0[n,:] = (1 + eps - degree[n]) * node_rep[n,:]; pad rows = 0; zero stats
__global__ void k_init(const float* __restrict__ nr,
                       const float* __restrict__ deg,
                       const float* __restrict__ eps) {
    if (blockIdx.x == 0) {
        int t = threadIdx.x;
        if (t < DIM_H) { g_sum1[t] = 0.f; g_sq1[t] = 0.f; }
        if (t < DIM_D) { g_sum2[t] = 0.f; g_sq2[t] = 0.f; }
    }
    int idx = blockIdx.x * blockDim.x + threadIdx.x;   // float4 index
    if (idx >= MPAD * (DIM_D / 4)) return;
    int row = idx >> 5;                                // 32 float4 per row
    float4 o = make_float4(0.f, 0.f, 0.f, 0.f);
    if (row < N_NODES) {
        float c = 1.0f + eps[0] - deg[row];
        float4 v = reinterpret_cast<const float4*>(nr)[idx];
        o = make_float4(c * v.x, c * v.y, c * v.z, c * v.w);
    }
    reinterpret_cast<float4*>(g_H0)[idx] = o;
}

__device__ __forceinline__ void red_add_v4(float* addr, float4 v) {
    asm volatile("red.global.add.v4.f32 [%0], {%1,%2,%3,%4};"
                 :: "l"(addr), "f"(v.x), "f"(v.y), "f"(v.z), "f"(v.w)
                 : "memory");
}

// one warp per edge: m = nr[src]+nr[dst]+ea; scatter-add to both endpoints.
// edge_attr is a one-shot 307MB stream -> evict-streaming load so the
// L2-resident node table (nr + H0) stays hot for the random gathers/atomics.
__global__ void k_edge_scatter(const float* __restrict__ nr,
                               const float* __restrict__ ea,
                               const int* __restrict__ src,
                               const int* __restrict__ dst) {
    int e = blockIdx.x * 8 + (threadIdx.x >> 5);
    if (e >= N_EDGES) return;
    int lane = threadIdx.x & 31;
    int s = src[e];
    int d = dst[e];
    float4 a = __ldg(reinterpret_cast<const float4*>(nr + (size_t)s * DIM_D) + lane);
    float4 b = __ldg(reinterpret_cast<const float4*>(nr + (size_t)d * DIM_D) + lane);
    float4 c = __ldcs(reinterpret_cast<const float4*>(ea + (size_t)e * DIM_D) + lane);
    float4 m = make_float4(a.x + b.x + c.x, a.y + b.y + c.y,
                           a.z + b.z + c.z, a.w + b.w + c.w);
    red_add_v4(g_H0 + (size_t)s * DIM_D + lane * 4, m);
    red_add_v4(g_H0 + (size_t)d * DIM_D + lane * 4, m);
}

// weights -> tf32 (both fit in one tiny grid)
__global__ void k_cvt_w(const float* __restrict__ W1, const float* __restrict__ W2) {
    int i = blockIdx.x * blockDim.x + threadIdx.x;
    if (i < DIM_H * DIM_D) {
        g_W1t[i] = f2tf32(W1[i]);
        g_W2t[i] = f2tf32(W2[i]);
    }
}

// ---------------- tf32 tensor-core GEMM, cp.async 3-stage pipeline ---------
// C[m,n] = sum_k A[m,k] * B[n,k].
// A is raw f32; each thread converts the 32 words it staged in-smem after the
// cp.async wait (BN==true additionally applies y=relu(x*s[k]+t[k]) and zeroes
// pad rows so downstream column stats stay clean). B is pre-converted tf32.
// Block 128x128, BK=32, 8 warps 4(M)x2(N), warp tile 32x64.
// Epilogue: store C (f32) and atomically accumulate per-column sum / sum-sq.

#define GSTAGES 3
#define TILE_WORDS (128 * 36)                   // one operand tile (padded)
#define STAGE_WORDS (2 * TILE_WORDS)            // A + B
#define GEMM_SMEM_BYTES (GSTAGES * STAGE_WORDS * 4)

template <bool BN>
__global__ __launch_bounds__(256, 2)
void k_gemm(const float* __restrict__ A, const uint32_t* __restrict__ Bt,
            float* __restrict__ C, int Ntot, int K,
            const float* __restrict__ bnS, const float* __restrict__ bnT,
            float* __restrict__ osum, float* __restrict__ osq) {
    extern __shared__ uint32_t sm[];
    __shared__ float sS[DIM_H], sT[DIM_H];
    const int tid  = threadIdx.x;
    const int warp = tid >> 5;
    const int lane = tid & 31;
    const int wm   = warp >> 1;
    const int wn   = warp & 1;
    const int g    = lane >> 2;
    const int tg   = lane & 3;
    const int mbase = blockIdx.y * 128;
    const int nbase = blockIdx.x * 128;

    if (BN) {
        for (int c = tid; c < K; c += 256) { sS[c] = bnS[c]; sT[c] = bnT[c]; }
    }

    int frow[4], fcol[4];
    #pragma unroll
    for (int it = 0; it < 4; it++) {
        int idx = tid + it * 256;
        frow[it] = idx >> 3;
        fcol[it] = (idx & 7) * 4;
    }
    const int iters = K >> 5;

    float acc[2][8][4] = {};

    auto issue = [&](int i) {
        uint32_t* as = sm + (i % GSTAGES) * STAGE_WORDS;
        uint32_t* bs = as + TILE_WORDS;
        #pragma unroll
        for (int it = 0; it < 4; it++) {
            const float*    ga = A  + (size_t)(mbase + frow[it]) * K + i * 32 + fcol[it];
            const uint32_t* gb = Bt + (size_t)(nbase + frow[it]) * K + i * 32 + fcol[it];
            uint32_t da = (uint32_t)__cvta_generic_to_shared(as + frow[it] * 36 + fcol[it]);
            uint32_t db = (uint32_t)__cvta_generic_to_shared(bs + frow[it] * 36 + fcol[it]);
            asm volatile("cp.async.cg.shared.global [%0], [%1], 16;" :: "r"(da), "l"(ga));
            asm volatile("cp.async.cg.shared.global [%0], [%1], 16;" :: "r"(db), "l"(gb));
        }
        asm volatile("cp.async.commit_group;");
    };

    issue(0);
    issue(1);

    for (int i = 0; i < iters; i++) {
        asm volatile("cp.async.wait_group 1;");
        __syncthreads();
        if (i + 2 < iters) issue(i + 2);
        else asm volatile("cp.async.commit_group;");   // keep group count in step

        uint32_t* as = sm + (i % GSTAGES) * STAGE_WORDS;
        const uint32_t* bs = as + TILE_WORDS;

        // --- in-place convert of this thread's staged A words -------------
        #pragma unroll
        for (int it = 0; it < 4; it++) {
            uint32_t* p = as + frow[it] * 36 + fcol[it];
            float4 v = *reinterpret_cast<const float4*>(p);
            if (BN) {
                int kk = i * 32 + fcol[it];
                if (mbase + frow[it] < N_NODES) {
                    v.x = fmaxf(fmaf(v.x, sS[kk + 0], sT[kk + 0]), 0.f);
                    v.y = fmaxf(fmaf(v.y, sS[kk + 1], sT[kk + 1]), 0.f);
                    v.z = fmaxf(fmaf(v.z, sS[kk + 2], sT[kk + 2]), 0.f);
                    v.w = fmaxf(fmaf(v.w, sS[kk + 3], sT[kk + 3]), 0.f);
                } else {
                    v = make_float4(0.f, 0.f, 0.f, 0.f);
                }
            }
            uint4 q;
            q.x = f2tf32(v.x); q.y = f2tf32(v.y);
            q.z = f2tf32(v.z); q.w = f2tf32(v.w);
            *reinterpret_cast<uint4*>(p) = q;
        }
        __syncthreads();

        #pragma unroll
        for (int ks = 0; ks < 4; ks++) {
            const int kc = ks * 8;
            uint32_t af[2][4];
            #pragma unroll
            for (int ii = 0; ii < 2; ii++) {
                int r = wm * 32 + ii * 16 + g;
                af[ii][0] = as[r * 36 + kc + tg];
                af[ii][1] = as[(r + 8) * 36 + kc + tg];
                af[ii][2] = as[r * 36 + kc + tg + 4];
                af[ii][3] = as[(r + 8) * 36 + kc + tg + 4];
            }
            #pragma unroll
            for (int j = 0; j < 8; j++) {
                int n = wn * 64 + j * 8 + g;
                uint32_t b0 = bs[n * 36 + kc + tg];
                uint32_t b1 = bs[n * 36 + kc + tg + 4];
                asm volatile(
                    "mma.sync.aligned.m16n8k8.row.col.f32.tf32.tf32.f32 "
                    "{%0,%1,%2,%3}, {%4,%5,%6,%7}, {%8,%9}, {%0,%1,%2,%3};"
                    : "+f"(acc[0][j][0]), "+f"(acc[0][j][1]),
                      "+f"(acc[0][j][2]), "+f"(acc[0][j][3])
                    : "r"(af[0][0]), "r"(af[0][1]), "r"(af[0][2]), "r"(af[0][3]),
                      "r"(b0), "r"(b1));
                asm volatile(
                    "mma.sync.aligned.m16n8k8.row.col.f32.tf32.tf32.f32 "
                    "{%0,%1,%2,%3}, {%4,%5,%6,%7}, {%8,%9}, {%0,%1,%2,%3};"
                    : "+f"(acc[1][j][0]), "+f"(acc[1][j][1]),
                      "+f"(acc[1][j][2]), "+f"(acc[1][j][3])
                    : "r"(af[1][0]), "r"(af[1][1]), "r"(af[1][2]), "r"(af[1][3]),
                      "r"(b0), "r"(b1));
            }
        }
        __syncthreads();
    }

    // --- store C (no guards: M padded, N multiple of 128) -----------------
    #pragma unroll
    for (int ii = 0; ii < 2; ii++) {
        int r0 = mbase + wm * 32 + ii * 16 + g;
        int r1 = r0 + 8;
        #pragma unroll
        for (int j = 0; j < 8; j++) {
            int c0 = nbase + wn * 64 + j * 8 + tg * 2;
            *reinterpret_cast<float2*>(C + (size_t)r0 * Ntot + c0) =
                make_float2(acc[ii][j][0], acc[ii][j][1]);
            *reinterpret_cast<float2*>(C + (size_t)r1 * Ntot + c0) =
                make_float2(acc[ii][j][2], acc[ii][j][3]);
        }
    }

    // --- fused column stats: reduce 32 warp-tile rows, atomic to global ---
    #pragma unroll
    for (int j = 0; j < 8; j++) {
        #pragma unroll
        for (int q = 0; q < 2; q++) {
            float a0 = acc[0][j][q],     a1 = acc[0][j][q + 2];
            float a2 = acc[1][j][q],     a3 = acc[1][j][q + 2];
            float s  = a0 + a1 + a2 + a3;
            float ss = a0 * a0 + a1 * a1 + a2 * a2 + a3 * a3;
            #pragma unroll
            for (int o = 4; o < 32; o <<= 1) {
                s  += __shfl_xor_sync(0xffffffffu, s,  o);
                ss += __shfl_xor_sync(0xffffffffu, ss, o);
            }
            if (g == 0) {
                int c = nbase + wn * 64 + j * 8 + tg * 2 + q;
                atomicAdd(&osum[c], s);
                atomicAdd(&osq[c], ss);
            }
        }
    }
}

// ---------------- BN params ------------------------------------------------

__global__ void k_bn_params(const float* __restrict__ sum,
                            const float* __restrict__ sq,
                            const float* __restrict__ gam,
                            const float* __restrict__ bet,
                            int C, float* __restrict__ oS, float* __restrict__ oT) {
    int c = threadIdx.x;
    if (c >= C) return;
    const float invN = 1.0f / (float)N_NODES;
    float mean = sum[c] * invN;
    float var  = sq[c] * invN - mean * mean;
    float s = gam[c] * rsqrtf(var + 1e-5f);
    oS[c] = s;
    oT[c] = bet[c] - mean * s;
}

// out = relu(bn2(X2)), X2 lives in g_H0 (f32, raw GEMM2 output)
__global__ void k_final(const float* __restrict__ s2,
                        const float* __restrict__ t2,
                        float* __restrict__ out) {
    int idx = blockIdx.x * blockDim.x + threadIdx.x;
    if (idx >= N_NODES * (DIM_D / 4)) return;
    int c0 = (idx & 31) * 4;
    float4 v = reinterpret_cast<const float4*>(g_H0)[idx];
    float4 o;
    o.x = fmaxf(fmaf(v.x, s2[c0 + 0], t2[c0 + 0]), 0.f);
    o.y = fmaxf(fmaf(v.y, s2[c0 + 1], t2[c0 + 1]), 0.f);
    o.z = fmaxf(fmaf(v.z, s2[c0 + 2], t2[c0 + 2]), 0.f);
    o.w = fmaxf(fmaf(v.w, s2[c0 + 3], t2[c0 + 3]), 0.f);
    reinterpret_cast<float4*>(out)[idx] = o;
}

// ---------------- launch ----------------------------------------------------

extern "C" void kernel_launch(void* const* d_in, const int* in_sizes, int n_in,
                              void* d_out, int out_size) {
    const float* node_rep  = (const float*)d_in[0];
    const float* edge_attr = (const float*)d_in[1];
    const float* degree    = (const float*)d_in[2];
    const float* eps       = (const float*)d_in[3];
    const float* W1        = (const float*)d_in[4];
    const float* gam1      = (const float*)d_in[5];
    const float* bet1      = (const float*)d_in[6];
    const float* W2        = (const float*)d_in[7];
    const float* gam2      = (const float*)d_in[8];
    const float* bet2      = (const float*)d_in[9];
    const int*   src       = (const int*)d_in[10];
    const int*   dst       = (const int*)d_in[11];
    float* out = (float*)d_out;

    float *pH0, *pX1, *psum1, *psq1, *psum2, *psq2, *ps1, *pt1, *ps2, *pt2;
    uint32_t *pW1t, *pW2t;
    cudaGetSymbolAddress((void**)&pH0, g_H0);
    cudaGetSymbolAddress((void**)&pX1, g_X1);
    cudaGetSymbolAddress((void**)&pW1t, g_W1t);
    cudaGetSymbolAddress((void**)&pW2t, g_W2t);
    cudaGetSymbolAddress((void**)&psum1, g_sum1);
    cudaGetSymbolAddress((void**)&psq1, g_sq1);
    cudaGetSymbolAddress((void**)&psum2, g_sum2);
    cudaGetSymbolAddress((void**)&psq2, g_sq2);
    cudaGetSymbolAddress((void**)&ps1, g_s1);
    cudaGetSymbolAddress((void**)&pt1, g_t1);
    cudaGetSymbolAddress((void**)&ps2, g_s2);
    cudaGetSymbolAddress((void**)&pt2, g_t2);

    cudaFuncSetAttribute(k_gemm<false>, cudaFuncAttributeMaxDynamicSharedMemorySize,
                         GEMM_SMEM_BYTES);
    cudaFuncSetAttribute(k_gemm<true>, cudaFuncAttributeMaxDynamicSharedMemorySize,
                         GEMM_SMEM_BYTES);

    k_init<<<(MPAD * (DIM_D / 4) + 255) / 256, 256>>>(node_rep, degree, eps);
    k_cvt_w<<<(DIM_H * DIM_D + 255) / 256, 256>>>(W1, W2);
    k_edge_scatter<<<N_EDGES / 8, 256>>>(node_rep, edge_attr, src, dst);

    dim3 grid1(DIM_H / 128, MPAD / 128);   // x fastest -> A tile L2 reuse
    k_gemm<false><<<grid1, 256, GEMM_SMEM_BYTES>>>((const float*)pH0, pW1t, pX1,
                                                   DIM_H, DIM_D, nullptr, nullptr,
                                                   psum1, psq1);
    k_bn_params<<<1, DIM_H>>>(psum1, psq1, gam1, bet1, DIM_H, ps1, pt1);

    dim3 grid2(DIM_D / 128, MPAD / 128);
    k_gemm<true><<<grid2, 256, GEMM_SMEM_BYTES>>>((const float*)pX1, pW2t, pH0,
                                                  DIM_D, DIM_H, ps1, pt1,
                                                  psum2, psq2);
    k_bn_params<<<1, DIM_D>>>(psum2, psq2, gam2, bet2, DIM_D, ps2, pt2);

    k_final<<<(N_NODES * (DIM_D / 4) + 255) / 256, 256>>>(ps2, pt2, out);
}